// round 16
// baseline (speedup 1.0000x reference)
#include <cuda_runtime.h>
#include <cuda_fp16.h>
#include <math.h>
#include <stdint.h>

#define Bq   2
#define Tq   2048
#define Cq   1024
#define Hq   16
#define HSq  64
#define FFq  4096
#define BTq  (Bq*Tq)          // 4096
#define EPSq 1e-5f

typedef long long ll;

// ---------------------------------------------------------------------------
// Scratch (device globals — allocation-free)
// ---------------------------------------------------------------------------
__device__ __half g_h  [(size_t)BTq*Cq];              // LN outputs (half)
__device__ __half g_qk [(size_t)2*BTq*Cq];            // [2][B*T][H*HS]
__device__ __half g_vt [(size_t)Cq*BTq];              // V^T scaled by 1/sum
__device__ __half g_S  [(size_t)Hq*Bq*Tq*Tq];         // exp'ed weights (half)
__device__ float  g_part [(size_t)Hq*Bq*16*Tq];       // partial sums per band
__device__ float  g_stats[(size_t)Hq*Bq*Tq];          // 1/sum per column
__device__ __half g_att[(size_t)BTq*Cq];
__device__ float  g_x1 [(size_t)BTq*Cq];              // residual fp32
__device__ __half g_ff [(size_t)BTq*FFq];
__device__ __half g_wqkt[(size_t)2*Cq*Cq];            // [2][H*HS][C]
__device__ __half g_wvt[(size_t)Cq*Cq];
__device__ __half g_wot[(size_t)Cq*Cq];               // [C][H*HS]
__device__ __half g_w1t[(size_t)FFq*Cq];              // [FF][C]
__device__ __half g_w2t[(size_t)Cq*FFq];              // [C][FF]

// ---------------------------------------------------------------------------
// helpers
// ---------------------------------------------------------------------------
__device__ __forceinline__ uint32_t smem_u32(const void* p) {
    uint32_t a;
    asm("{ .reg .u64 t; cvta.to.shared.u64 t, %1; cvt.u32.u64 %0, t; }"
        : "=r"(a) : "l"(p));
    return a;
}
__device__ __forceinline__ void cpasync16(uint32_t dst, const void* src) {
    asm volatile("cp.async.cg.shared.global [%0], [%1], 16;"
                 :: "r"(dst), "l"(src));
}
#define CP_COMMIT() asm volatile("cp.async.commit_group;" ::: "memory")
#define CP_WAIT1()  asm volatile("cp.async.wait_group 1;" ::: "memory")

__device__ __forceinline__ void ldsm4(uint32_t* r, uint32_t a) {
    asm volatile("ldmatrix.sync.aligned.m8n8.x4.shared.b16 {%0,%1,%2,%3}, [%4];"
        : "=r"(r[0]), "=r"(r[1]), "=r"(r[2]), "=r"(r[3]) : "r"(a));
}
__device__ __forceinline__ void mma_f16(float* c, const uint32_t* a, const uint32_t* b) {
    asm volatile(
        "mma.sync.aligned.m16n8k16.row.col.f32.f16.f16.f32 "
        "{%0,%1,%2,%3},{%4,%5,%6,%7},{%8,%9},{%0,%1,%2,%3};"
        : "+f"(c[0]), "+f"(c[1]), "+f"(c[2]), "+f"(c[3])
        : "r"(a[0]), "r"(a[1]), "r"(a[2]), "r"(a[3]), "r"(b[0]), "r"(b[1]));
}

// ---------------------------------------------------------------------------
// LayerNorm (half output)
// ---------------------------------------------------------------------------
__global__ __launch_bounds__(256)
void layernorm_kernel(const float* __restrict__ x, const float* __restrict__ w,
                      __half* __restrict__ out)
{
    ll r = blockIdx.x;
    int t = threadIdx.x;
    const float4* xr = reinterpret_cast<const float4*>(x + r * Cq);
    float4 v = xr[t];
    float sum = v.x + v.y + v.z + v.w;
    float sq  = v.x*v.x + v.y*v.y + v.z*v.z + v.w*v.w;
    #pragma unroll
    for (int o = 16; o; o >>= 1) {
        sum += __shfl_xor_sync(0xffffffffu, sum, o);
        sq  += __shfl_xor_sync(0xffffffffu, sq,  o);
    }
    __shared__ float s1[8], s2[8];
    __shared__ float mu_s, rstd_s;
    int wid = t >> 5, lane = t & 31;
    if (lane == 0) { s1[wid] = sum; s2[wid] = sq; }
    __syncthreads();
    if (t == 0) {
        float S = 0.f, Q = 0.f;
        #pragma unroll
        for (int i = 0; i < 8; i++) { S += s1[i]; Q += s2[i]; }
        float mu  = S * (1.0f / Cq);
        float var = Q * (1.0f / Cq) - mu * mu;
        mu_s = mu; rstd_s = rsqrtf(var + EPSq);
    }
    __syncthreads();
    float mu = mu_s, rstd = rstd_s;
    float4 ww = reinterpret_cast<const float4*>(w)[t];
    __half2 h0 = __halves2half2(__float2half_rn((v.x - mu) * rstd * ww.x),
                                __float2half_rn((v.y - mu) * rstd * ww.y));
    __half2 h1 = __halves2half2(__float2half_rn((v.z - mu) * rstd * ww.z),
                                __float2half_rn((v.w - mu) * rstd * ww.w));
    __half2* op = reinterpret_cast<__half2*>(out + r * Cq);
    op[t * 2 + 0] = h0;
    op[t * 2 + 1] = h1;
}

// ---------------------------------------------------------------------------
// ALL 6 weight transposes in ONE launch (fp32 src -> half dst)
// ---------------------------------------------------------------------------
__global__ __launch_bounds__(256)
void transpose_all_kernel(const float* __restrict__ Wq, const float* __restrict__ Wk,
                          const float* __restrict__ Wv, const float* __restrict__ Wo,
                          const float* __restrict__ W1, const float* __restrict__ W2,
                          __half* __restrict__ dqk, __half* __restrict__ dv,
                          __half* __restrict__ dwo, __half* __restrict__ dw1,
                          __half* __restrict__ dw2)
{
    int t = blockIdx.x;
    const float* src; __half* dst; int lds, ldd, r0, cc0;
    if (t < 3072) {
        int m = t >> 10;
        int r = t & 1023;
        int head = r >> 6;
        int rem  = r & 63;
        const float* S = (m == 0) ? Wq : (m == 1) ? Wk : Wv;
        __half* D = (m == 0) ? dqk : (m == 1) ? (dqk + (size_t)Cq * Cq) : dv;
        src = S + (ll)head * Cq * HSq;
        dst = D + (ll)head * HSq * Cq;
        lds = HSq; ldd = Cq;
        r0  = (rem >> 1) * 32;
        cc0 = (rem & 1) * 32;
    } else if (t < 4096) {
        int r = t - 3072;
        src = Wo; dst = dwo; lds = Cq; ldd = Cq;
        r0 = (r >> 5) * 32; cc0 = (r & 31) * 32;
    } else if (t < 8192) {
        int r = t - 4096;
        src = W1; dst = dw1; lds = FFq; ldd = Cq;
        r0 = (r >> 7) * 32; cc0 = (r & 127) * 32;
    } else {
        int r = t - 8192;
        src = W2; dst = dw2; lds = Cq; ldd = FFq;
        r0 = (r >> 5) * 32; cc0 = (r & 31) * 32;
    }

    __shared__ float tile[32][33];
    int tx = threadIdx.x & 31, ty = threadIdx.x >> 5;
    #pragma unroll
    for (int p = 0; p < 4; p++)
        tile[ty + p * 8][tx] = src[(ll)(r0 + ty + p * 8) * lds + cc0 + tx];
    __syncthreads();
    #pragma unroll
    for (int p = 0; p < 4; p++)
        dst[(ll)(cc0 + ty + p * 8) * ldd + r0 + tx] =
            __float2half_rn(tile[tx][ty + p * 8]);
}

// ---------------------------------------------------------------------------
// fp16 mma.sync GEMM (m16n8k16) — 5-stage ring, 2 K32-chunks/iter,
// fragment double-buffering, nk-guarded prologue.
// MMODE: 0 = normal, 1 = strict-lower scores tile (no per-elem compare),
//        2 = diagonal scores tile (n0 = m0, per-elem compare).
// STATS (MMODE 1/2): w = ex2.approx.f16x2(acc*alpha), fp32 col sums,
//                    smem-staged coalesced S stores.
// VSCALE (V proj): CTRANS store scaled by 1/sum.
// CAUSAL_K: m-tiles processed in reverse order (heavy first).
// ---------------------------------------------------------------------------
template<int BN, bool BIAS, bool RELU, bool RES, bool CAUSAL_K, int MMODE,
         bool CTRANS, bool CHALF, bool STATS, bool VSCALE>
__global__ __launch_bounds__(256, 2)
void mma_gemm(const __half* __restrict__ A, ll sA1, ll sA2,
              const __half* __restrict__ Bm, ll sB1, ll sB2,
              const float* __restrict__ bias, const float* __restrict__ bias2,
              const float* __restrict__ res,
              void* __restrict__ C, ll sC1, ll sC2,
              float* __restrict__ part,
              int Z2, int K, int lda, int ldb, int ldc, float alpha)
{
    constexpr int BM   = 128;
    constexpr int ROWB = 80;
    constexpr int A_TILE = BM * ROWB;
    constexpr int B_TILE = BN * ROWB;
    constexpr int STAGE  = A_TILE + B_TILE;
    constexpr int NTPW = BN / 16;
    constexpr int NGRP = NTPW / 2;
    constexpr int WN   = BN / 2;
    constexpr int SROW = 136;            // staging row stride (halves)

    extern __shared__ __align__(16) char dsm[];
    const uint32_t sb = smem_u32(dsm);

    const int tid  = threadIdx.x;
    const int lane = tid & 31;
    const int wid  = tid >> 5;
    const int warpM = wid & 3;
    const int warpN = wid >> 2;

    const int z  = blockIdx.z;
    const int z1 = z / Z2, z2 = z - z1 * Z2;
    const int myb = CAUSAL_K ? (int)(gridDim.y - 1 - blockIdx.y) : (int)blockIdx.y;
    const int m0 = myb * BM;
    const int n0 = (MMODE == 2) ? m0 : (int)blockIdx.x * BN;
    if (MMODE == 1 && n0 + BN > m0) return;   // keep only strict-lower tiles

    const __half* Ap = A  + z1 * sA1 + z2 * sA2;
    const __half* Bp = Bm + z1 * sB1 + z2 * sB2;
    float*  Cf = reinterpret_cast<float*>(C)  + z1 * sC1 + z2 * sC2;
    __half* Ch = reinterpret_cast<__half*>(C) + z1 * sC1 + z2 * sC2;
    const float* biasp = BIAS ? (z1 ? bias2 : bias) : nullptr;

    const int Keff = CAUSAL_K ? min(K, m0 + BM) : K;
    const int nk = Keff >> 5;

    const int lr = tid >> 2;
    const int lk = tid & 3;
    const __half* a_g = Ap + (ll)(m0 + lr) * lda + lk * 8;
    const __half* b_g = Bp + (ll)(n0 + lr) * ldb + lk * 8;
    const uint32_t a_off = (uint32_t)(lr * ROWB + lk * 16);
    const uint32_t b_off = a_off;

    #define ISSUE(t)                                                          \
    {                                                                         \
        int k0 = (t) << 5;                                                    \
        uint32_t as = sb + ((t) % 5) * STAGE;                                 \
        uint32_t bs = as + A_TILE;                                            \
        cpasync16(as + a_off, a_g + k0);                                      \
        cpasync16(as + a_off + 64 * ROWB, a_g + k0 + 64 * (ll)lda);           \
        cpasync16(bs + b_off, b_g + k0);                                      \
        if (BN == 128)                                                        \
            cpasync16(bs + b_off + 64 * ROWB, b_g + k0 + 64 * (ll)ldb);       \
    }

    const uint32_t a_lmoff =
        (uint32_t)((warpM * 32 + (lane & 7) + ((lane >> 3) & 1) * 8) * ROWB
                   + ((lane >> 4) & 1) * 16);
    const uint32_t b_lmoff =
        (uint32_t)((warpN * WN + (lane & 7) + ((lane >> 4) & 1) * 8) * ROWB
                   + ((lane >> 3) & 1) * 16);

    float acc[2][NTPW][4];
    #pragma unroll
    for (int i = 0; i < 2; i++)
        #pragma unroll
        for (int j = 0; j < NTPW; j++)
            #pragma unroll
            for (int r = 0; r < 4; r++) acc[i][j][r] = 0.f;

    uint32_t fa[2][2][4];
    uint32_t fb[2][NTPW][2];

    #define LOADF(buf, stg_a, ksv)                                            \
    {                                                                         \
        uint32_t asx = (stg_a);                                               \
        uint32_t bsx = asx + A_TILE;                                          \
        _Pragma("unroll")                                                     \
        for (int mt = 0; mt < 2; mt++)                                        \
            ldsm4(fa[buf][mt], asx + a_lmoff + mt * (16 * ROWB) + (ksv) * 32);\
        _Pragma("unroll")                                                     \
        for (int ng = 0; ng < NGRP; ng++) {                                   \
            uint32_t r4[4];                                                   \
            ldsm4(r4, bsx + b_lmoff + ng * (16 * ROWB) + (ksv) * 32);         \
            fb[buf][2*ng][0] = r4[0]; fb[buf][2*ng][1] = r4[1];               \
            fb[buf][2*ng+1][0] = r4[2]; fb[buf][2*ng+1][1] = r4[3];           \
        }                                                                     \
    }
    #define MMAF(buf)                                                         \
    {                                                                         \
        _Pragma("unroll")                                                     \
        for (int mt = 0; mt < 2; mt++)                                        \
            _Pragma("unroll")                                                 \
            for (int nt = 0; nt < NTPW; nt++)                                 \
                mma_f16(acc[mt][nt], fa[buf][mt], fb[buf][nt]);               \
    }

    ISSUE(0); CP_COMMIT();
    if (1 < nk) { ISSUE(1); } CP_COMMIT();
    if (2 < nk) { ISSUE(2); } CP_COMMIT();

    for (int t = 0; t < nk; t += 2) {
        CP_WAIT1();
        __syncthreads();
        if (t + 3 < nk) { ISSUE(t + 3); }
        CP_COMMIT();
        if (t + 4 < nk) { ISSUE(t + 4); }
        CP_COMMIT();

        uint32_t st0 = sb + ((t)     % 5) * STAGE;
        uint32_t st1 = sb + ((t + 1) % 5) * STAGE;
        LOADF(0, st0, 0);
        LOADF(1, st0, 1);
        MMAF(0);
        LOADF(0, st1, 0);
        MMAF(1);
        LOADF(1, st1, 1);
        MMAF(0);
        MMAF(1);
    }
    #undef ISSUE
    #undef LOADF
    #undef MMAF
    __syncthreads();

    // epilogue
    float*  scr = reinterpret_cast<float*>(dsm);
    __half* stg = reinterpret_cast<__half*>(dsm + 4096);
    #pragma unroll
    for (int nt = 0; nt < NTPW; nt++) {
        int col = n0 + warpN * WN + nt * 8 + (lane & 3) * 2;
        float b0 = 0.f, b1 = 0.f;
        if (BIAS) {
            float2 bb = *reinterpret_cast<const float2*>(biasp + col);
            b0 = bb.x; b1 = bb.y;
        }
        float cs0 = 0.f, cs1 = 0.f;
        #pragma unroll
        for (int mt = 0; mt < 2; mt++) {
            int row0 = m0 + warpM * 32 + mt * 16 + (lane >> 2);
            #pragma unroll
            for (int rr = 0; rr < 2; rr++) {
                int row = row0 + rr * 8;
                float v0 = acc[mt][nt][rr * 2 + 0] * alpha + b0;
                float v1 = acc[mt][nt][rr * 2 + 1] * alpha + b1;
                if (RELU) { v0 = fmaxf(v0, 0.f); v1 = fmaxf(v1, 0.f); }
                if (RES) {
                    float2 rv = *reinterpret_cast<const float2*>(
                        res + (ll)row * ldc + col);
                    v0 += rv.x; v1 += rv.y;
                }
                if (STATS) {
                    // alpha already includes log2(e): v is the ex2 exponent
                    float u0 = v0, u1 = v1;
                    if (MMODE == 2) {
                        u0 = (col     > row) ? -60.f : u0;
                        u1 = (col + 1 > row) ? -60.f : u1;
                    }
                    __half2 hu = __floats2half2_rn(u0, u1);
                    uint32_t hw;
                    asm("ex2.approx.f16x2 %0, %1;"
                        : "=r"(hw) : "r"(*reinterpret_cast<uint32_t*>(&hu)));
                    __half2 hwv = *reinterpret_cast<__half2*>(&hw);
                    float2 wf = __half22float2(hwv);
                    cs0 += wf.x; cs1 += wf.y;
                    *reinterpret_cast<__half2*>(
                        stg + (row - m0) * SROW + (col - n0)) = hwv;
                } else if (CHALF) {
                    if (CTRANS) {
                        if (VSCALE) {
                            float sc = part[((col >> 6) * Bq + (row >> 11)) * Tq
                                            + (row & 2047)];
                            v0 *= sc; v1 *= sc;
                        }
                        Ch[(ll)col * ldc + row]       = __float2half_rn(v0);
                        Ch[(ll)(col + 1) * ldc + row] = __float2half_rn(v1);
                    } else {
                        *reinterpret_cast<__half2*>(Ch + (ll)row * ldc + col) =
                            __halves2half2(__float2half_rn(v0), __float2half_rn(v1));
                    }
                } else {
                    if (CTRANS) {
                        Cf[(ll)col * ldc + row] = v0;
                        Cf[(ll)(col + 1) * ldc + row] = v1;
                    } else {
                        *reinterpret_cast<float2*>(Cf + (ll)row * ldc + col) =
                            make_float2(v0, v1);
                    }
                }
            }
        }
        if (STATS) {
            #pragma unroll
            for (int off = 4; off <= 16; off <<= 1) {
                cs0 += __shfl_xor_sync(0xffffffffu, cs0, off);
                cs1 += __shfl_xor_sync(0xffffffffu, cs1, off);
            }
            if ((lane >> 2) == 0) {
                int c = warpN * WN + nt * 8 + lane * 2;
                scr[warpM * BN + c]     = cs0;
                scr[warpM * BN + c + 1] = cs1;
            }
        }
    }
    if (STATS) {
        __syncthreads();
        if (tid < BN) {
            float s = scr[tid] + scr[BN + tid] + scr[2 * BN + tid] + scr[3 * BN + tid];
            part[((ll)z * 16 + blockIdx.y) * Tq + n0 + tid] = s;
        }
        const int cr = tid >> 4;
        const int cc = (tid & 15) * 8;
        #pragma unroll
        for (int r = 0; r < 8; r++) {
            int row = cr + r * 16;
            uint4 v = *reinterpret_cast<const uint4*>(stg + row * SROW + cc);
            *reinterpret_cast<uint4*>(Ch + (ll)(m0 + row) * ldc + n0 + cc) = v;
        }
    }
}

// combine 128-row band partial sums -> 1/sum per column
__global__ __launch_bounds__(256)
void stats_combine_kernel(const float* __restrict__ part,
                          float* __restrict__ stats)
{
    const int z = blockIdx.y;
    const int j = blockIdx.x * 256 + threadIdx.x;
    float s = 0.f;
    for (int p = j >> 7; p < 16; p++)
        s += part[((ll)z * 16 + p) * Tq + j];
    stats[(ll)z * Tq + j] = 1.0f / s;
}

// ---------------------------------------------------------------------------
// Launch sequence
// ---------------------------------------------------------------------------
extern "C" void kernel_launch(void* const* d_in, const int* in_sizes, int n_in,
                              void* d_out, int out_size)
{
    const float* x     = (const float*)d_in[0];
    const float* ln1_w = (const float*)d_in[1];
    const float* Wq    = (const float*)d_in[2];
    const float* bq    = (const float*)d_in[3];
    const float* Wk    = (const float*)d_in[4];
    const float* bk    = (const float*)d_in[5];
    const float* Wv    = (const float*)d_in[6];
    const float* bv    = (const float*)d_in[7];
    const float* Wo    = (const float*)d_in[8];
    const float* bo    = (const float*)d_in[9];
    const float* ln2_w = (const float*)d_in[10];
    const float* W1    = (const float*)d_in[11];
    const float* b1    = (const float*)d_in[12];
    const float* W2    = (const float*)d_in[13];
    const float* b2    = (const float*)d_in[14];
    float* out = (float*)d_out;

    #define GETP(sym, var, ty) void* var##_; cudaGetSymbolAddress(&var##_, sym); \
                               ty* var = (ty*)var##_;
    GETP(g_h, ph, __half)  GETP(g_qk, pqk, __half)  GETP(g_vt, pvt, __half)
    GETP(g_S, pS, __half)
    GETP(g_part, ppart, float)  GETP(g_stats, pstats, float)
    GETP(g_att, patt, __half)  GETP(g_x1, px1, float)  GETP(g_ff, pff, __half)
    GETP(g_wqkt, pwqkt, __half)
    GETP(g_wvt, pwvt, __half)
    GETP(g_wot, pwot, __half)  GETP(g_w1t, pw1t, __half)  GETP(g_w2t, pw2t, __half)
    #undef GETP

    const int SM128 = 5 * (10240 + 10240);   // 102400
    const int SM64  = 5 * (10240 + 5120);    // 76800
    const float AL2E = 0.125f * 1.4426950408889634f;

    auto kQK  = mma_gemm<128,true ,false,false,false,0,false,true ,false,false>;
    auto kV   = mma_gemm<128,true ,false,false,false,0,true ,true ,false,true >;
    auto kScL = mma_gemm<128,false,false,false,false,1,false,false,true ,false>;
    auto kScD = mma_gemm<128,false,false,false,false,2,false,false,true ,false>;
    auto kAV  = mma_gemm<64 ,false,false,false,true ,0,false,true ,false,false>;
    auto kBR  = mma_gemm<128,true ,false,true ,false,0,false,false,false,false>;
    auto kFF1 = mma_gemm<64 ,true ,true ,false,false,0,false,true ,false,false>;
    cudaFuncSetAttribute(kQK,  cudaFuncAttributeMaxDynamicSharedMemorySize, SM128);
    cudaFuncSetAttribute(kV,   cudaFuncAttributeMaxDynamicSharedMemorySize, SM128);
    cudaFuncSetAttribute(kScL, cudaFuncAttributeMaxDynamicSharedMemorySize, SM128);
    cudaFuncSetAttribute(kScD, cudaFuncAttributeMaxDynamicSharedMemorySize, SM128);
    cudaFuncSetAttribute(kAV,  cudaFuncAttributeMaxDynamicSharedMemorySize, SM64);
    cudaFuncSetAttribute(kBR,  cudaFuncAttributeMaxDynamicSharedMemorySize, SM128);
    cudaFuncSetAttribute(kFF1, cudaFuncAttributeMaxDynamicSharedMemorySize, SM64);

    // #0 : ALL weight transposes fused
    transpose_all_kernel<<<12288, 256>>>(Wq, Wk, Wv, Wo, W1, W2,
                                         pwqkt, pwvt, pwot, pw1t, pw2t);
    // #1 : LN1
    layernorm_kernel<<<BTq, 256>>>(x, ln1_w, ph);

    // #2 : QK projections (batched z=2)
    {
        dim3 gridQK(Cq / 128, BTq / 128, 2);
        kQK<<<gridQK, 256, SM128>>>(ph, 0, 0, pwqkt, (ll)Cq*Cq, 0, bq, bk, nullptr,
                                    pqk, (ll)BTq*Cq, 0, nullptr,
                                    1, Cq, Cq, Cq, Cq, 1.0f);
    }
    // #3 : scores, strict-lower tiles (no per-element compare)  <-- ncu slot
    {
        dim3 grid(Tq / 128, Tq / 128, Hq * Bq);
        kScL<<<grid, 256, SM128>>>(
            pqk, (ll)HSq, (ll)Tq * Cq,
            pqk + (ll)BTq * Cq, (ll)HSq, (ll)Tq * Cq,
            nullptr, nullptr, nullptr,
            pS, (ll)Bq * Tq * Tq, (ll)Tq * Tq,
            ppart,
            Bq, HSq, Cq, Cq, Tq, AL2E);
    }
    // #4 : scores, diagonal tiles (masked)
    {
        dim3 grid(1, Tq / 128, Hq * Bq);
        kScD<<<grid, 256, SM128>>>(
            pqk, (ll)HSq, (ll)Tq * Cq,
            pqk + (ll)BTq * Cq, (ll)HSq, (ll)Tq * Cq,
            nullptr, nullptr, nullptr,
            pS, (ll)Bq * Tq * Tq, (ll)Tq * Tq,
            ppart,
            Bq, HSq, Cq, Cq, Tq, AL2E);
    }
    // #5 : combine band sums -> 1/sum
    {
        dim3 g2(Tq / 256, Hq * Bq);
        stats_combine_kernel<<<g2, 256>>>(ppart, pstats);
    }
    // #6 : V projection (writes V^T * 1/sum, fused scaling)
    {
        dim3 gridV(Cq / 128, BTq / 128, 1);
        kV <<<gridV, 256, SM128>>>(ph, 0, 0, pwvt, 0, 0, bv, bv, nullptr,
                                   pvt, 0, 0, pstats,
                                   1, Cq, Cq, Cq, BTq, 1.0f);
    }
    // #7 : att = S @ Vs (plain causal GEMM, heavy tiles first)
    {
        dim3 grid(1, Tq / 128, Hq * Bq);
        kAV<<<grid, 256, SM64>>>(
            pS, (ll)Bq * Tq * Tq, (ll)Tq * Tq,
            pvt, (ll)HSq * BTq, (ll)Tq,
            nullptr, nullptr, nullptr,
            patt, (ll)HSq, (ll)Tq * Cq,
            nullptr,
            Bq, Tq, Tq, BTq, Cq, 1.0f);
    }
    // #8 : x1 = x + att @ Wo + bo (fp32 out)
    {
        dim3 grid(Cq / 128, BTq / 128, 1);
        kBR<<<grid, 256, SM128>>>(patt, 0, 0, pwot, 0, 0, bo, bo, x,
                                  px1, 0, 0, nullptr, 1, Cq, Cq, Cq, Cq, 1.0f);
    }
    // #9 : LN2, #10 : FF1 (half out, BN=64 — 6.92 waves)
    layernorm_kernel<<<BTq, 256>>>(px1, ln2_w, ph);
    {
        dim3 grid(FFq / 64, BTq / 128, 1);
        kFF1<<<grid, 256, SM64>>>(ph, 0, 0, pw1t, 0, 0, b1, b1, nullptr,
                                  pff, 0, 0, nullptr, 1, Cq, Cq, Cq, FFq, 1.0f);
    }
    // #11: out = x1 + ff @ W2 + b2 (fp32 out)
    {
        dim3 grid(Cq / 128, BTq / 128, 1);
        kBR<<<grid, 256, SM128>>>(pff, 0, 0, pw2t, 0, 0, b2, b2, px1,
                                  out, 0, 0, nullptr, 1, FFq, FFq, FFq, Cq, 1.0f);
    }
}

// round 17
// speedup vs baseline: 1.0536x; 1.0536x over previous
#include <cuda_runtime.h>
#include <cuda_fp16.h>
#include <math.h>
#include <stdint.h>

#define Bq   2
#define Tq   2048
#define Cq   1024
#define Hq   16
#define HSq  64
#define FFq  4096
#define BTq  (Bq*Tq)          // 4096
#define EPSq 1e-5f

typedef long long ll;

// ---------------------------------------------------------------------------
// Scratch (device globals — allocation-free)
// ---------------------------------------------------------------------------
__device__ __half g_h  [(size_t)BTq*Cq];              // LN outputs (half)
__device__ __half g_qk [(size_t)2*BTq*Cq];            // [2][B*T][H*HS]
__device__ __half g_vt [(size_t)Cq*BTq];              // V^T scaled by 1/sum
__device__ __half g_S  [(size_t)Hq*Bq*Tq*Tq];         // exp'ed weights (half)
__device__ float  g_part [(size_t)Hq*Bq*16*Tq];       // partial sums per band
__device__ float  g_stats[(size_t)Hq*Bq*Tq];          // 1/sum per column
__device__ __half g_att[(size_t)BTq*Cq];
__device__ float  g_x1 [(size_t)BTq*Cq];              // residual fp32
__device__ __half g_ff [(size_t)BTq*FFq];
__device__ __half g_wqkt[(size_t)2*Cq*Cq];            // [2][H*HS][C]
__device__ __half g_wvt[(size_t)Cq*Cq];
__device__ __half g_wot[(size_t)Cq*Cq];               // [C][H*HS]
__device__ __half g_w1t[(size_t)FFq*Cq];              // [FF][C]
__device__ __half g_w2t[(size_t)Cq*FFq];              // [C][FF]

// ---------------------------------------------------------------------------
// helpers
// ---------------------------------------------------------------------------
__device__ __forceinline__ uint32_t smem_u32(const void* p) {
    uint32_t a;
    asm("{ .reg .u64 t; cvta.to.shared.u64 t, %1; cvt.u32.u64 %0, t; }"
        : "=r"(a) : "l"(p));
    return a;
}
__device__ __forceinline__ void cpasync16(uint32_t dst, const void* src) {
    asm volatile("cp.async.cg.shared.global [%0], [%1], 16;"
                 :: "r"(dst), "l"(src));
}
#define CP_COMMIT() asm volatile("cp.async.commit_group;" ::: "memory")
#define CP_WAIT1()  asm volatile("cp.async.wait_group 1;" ::: "memory")

__device__ __forceinline__ void ldsm4(uint32_t* r, uint32_t a) {
    asm volatile("ldmatrix.sync.aligned.m8n8.x4.shared.b16 {%0,%1,%2,%3}, [%4];"
        : "=r"(r[0]), "=r"(r[1]), "=r"(r[2]), "=r"(r[3]) : "r"(a));
}
__device__ __forceinline__ void mma_f16(float* c, const uint32_t* a, const uint32_t* b) {
    asm volatile(
        "mma.sync.aligned.m16n8k16.row.col.f32.f16.f16.f32 "
        "{%0,%1,%2,%3},{%4,%5,%6,%7},{%8,%9},{%0,%1,%2,%3};"
        : "+f"(c[0]), "+f"(c[1]), "+f"(c[2]), "+f"(c[3])
        : "r"(a[0]), "r"(a[1]), "r"(a[2]), "r"(a[3]), "r"(b[0]), "r"(b[1]));
}

// ---------------------------------------------------------------------------
// LayerNorm (half output)
// ---------------------------------------------------------------------------
__global__ __launch_bounds__(256)
void layernorm_kernel(const float* __restrict__ x, const float* __restrict__ w,
                      __half* __restrict__ out)
{
    ll r = blockIdx.x;
    int t = threadIdx.x;
    const float4* xr = reinterpret_cast<const float4*>(x + r * Cq);
    float4 v = xr[t];
    float sum = v.x + v.y + v.z + v.w;
    float sq  = v.x*v.x + v.y*v.y + v.z*v.z + v.w*v.w;
    #pragma unroll
    for (int o = 16; o; o >>= 1) {
        sum += __shfl_xor_sync(0xffffffffu, sum, o);
        sq  += __shfl_xor_sync(0xffffffffu, sq,  o);
    }
    __shared__ float s1[8], s2[8];
    __shared__ float mu_s, rstd_s;
    int wid = t >> 5, lane = t & 31;
    if (lane == 0) { s1[wid] = sum; s2[wid] = sq; }
    __syncthreads();
    if (t == 0) {
        float S = 0.f, Q = 0.f;
        #pragma unroll
        for (int i = 0; i < 8; i++) { S += s1[i]; Q += s2[i]; }
        float mu  = S * (1.0f / Cq);
        float var = Q * (1.0f / Cq) - mu * mu;
        mu_s = mu; rstd_s = rsqrtf(var + EPSq);
    }
    __syncthreads();
    float mu = mu_s, rstd = rstd_s;
    float4 ww = reinterpret_cast<const float4*>(w)[t];
    __half2 h0 = __halves2half2(__float2half_rn((v.x - mu) * rstd * ww.x),
                                __float2half_rn((v.y - mu) * rstd * ww.y));
    __half2 h1 = __halves2half2(__float2half_rn((v.z - mu) * rstd * ww.z),
                                __float2half_rn((v.w - mu) * rstd * ww.w));
    __half2* op = reinterpret_cast<__half2*>(out + r * Cq);
    op[t * 2 + 0] = h0;
    op[t * 2 + 1] = h1;
}

// ---------------------------------------------------------------------------
// ALL 6 weight transposes in ONE launch (fp32 src -> half dst)
// ---------------------------------------------------------------------------
__global__ __launch_bounds__(256)
void transpose_all_kernel(const float* __restrict__ Wq, const float* __restrict__ Wk,
                          const float* __restrict__ Wv, const float* __restrict__ Wo,
                          const float* __restrict__ W1, const float* __restrict__ W2,
                          __half* __restrict__ dqk, __half* __restrict__ dv,
                          __half* __restrict__ dwo, __half* __restrict__ dw1,
                          __half* __restrict__ dw2)
{
    int t = blockIdx.x;
    const float* src; __half* dst; int lds, ldd, r0, cc0;
    if (t < 3072) {
        int m = t >> 10;
        int r = t & 1023;
        int head = r >> 6;
        int rem  = r & 63;
        const float* S = (m == 0) ? Wq : (m == 1) ? Wk : Wv;
        __half* D = (m == 0) ? dqk : (m == 1) ? (dqk + (size_t)Cq * Cq) : dv;
        src = S + (ll)head * Cq * HSq;
        dst = D + (ll)head * HSq * Cq;
        lds = HSq; ldd = Cq;
        r0  = (rem >> 1) * 32;
        cc0 = (rem & 1) * 32;
    } else if (t < 4096) {
        int r = t - 3072;
        src = Wo; dst = dwo; lds = Cq; ldd = Cq;
        r0 = (r >> 5) * 32; cc0 = (r & 31) * 32;
    } else if (t < 8192) {
        int r = t - 4096;
        src = W1; dst = dw1; lds = FFq; ldd = Cq;
        r0 = (r >> 7) * 32; cc0 = (r & 127) * 32;
    } else {
        int r = t - 8192;
        src = W2; dst = dw2; lds = Cq; ldd = FFq;
        r0 = (r >> 5) * 32; cc0 = (r & 31) * 32;
    }

    __shared__ float tile[32][33];
    int tx = threadIdx.x & 31, ty = threadIdx.x >> 5;
    #pragma unroll
    for (int p = 0; p < 4; p++)
        tile[ty + p * 8][tx] = src[(ll)(r0 + ty + p * 8) * lds + cc0 + tx];
    __syncthreads();
    #pragma unroll
    for (int p = 0; p < 4; p++)
        dst[(ll)(cc0 + ty + p * 8) * ldd + r0 + tx] =
            __float2half_rn(tile[tx][ty + p * 8]);
}

// ---------------------------------------------------------------------------
// fp16 mma.sync GEMM (m16n8k16) — 5-stage ring, 2 K32-chunks/iter,
// fragment double-buffering, nk-guarded prologue.
// MASK (scores): tiles above diagonal skipped; diagonal tiles (n0==m0) take
// the per-element-compare path via a uniform branch; strict-lower tiles are
// compare-free.  STATS: w = ex2.approx.f16x2(acc*alpha), fp32 col sums,
// smem-staged coalesced S stores.  VSCALE: CTRANS store scaled by 1/sum.
// CAUSAL_K: m-tiles processed in reverse order.
// ---------------------------------------------------------------------------
template<int BN, bool BIAS, bool RELU, bool RES, bool CAUSAL_K, bool MASK,
         bool CTRANS, bool CHALF, bool STATS, bool VSCALE>
__global__ __launch_bounds__(256, 2)
void mma_gemm(const __half* __restrict__ A, ll sA1, ll sA2,
              const __half* __restrict__ Bm, ll sB1, ll sB2,
              const float* __restrict__ bias, const float* __restrict__ bias2,
              const float* __restrict__ res,
              void* __restrict__ C, ll sC1, ll sC2,
              float* __restrict__ part,
              int Z2, int K, int lda, int ldb, int ldc, float alpha)
{
    constexpr int BM   = 128;
    constexpr int ROWB = 80;
    constexpr int A_TILE = BM * ROWB;
    constexpr int B_TILE = BN * ROWB;
    constexpr int STAGE  = A_TILE + B_TILE;
    constexpr int NTPW = BN / 16;
    constexpr int NGRP = NTPW / 2;
    constexpr int WN   = BN / 2;
    constexpr int SROW = 136;            // staging row stride (halves)

    extern __shared__ __align__(16) char dsm[];
    const uint32_t sb = smem_u32(dsm);

    const int tid  = threadIdx.x;
    const int lane = tid & 31;
    const int wid  = tid >> 5;
    const int warpM = wid & 3;
    const int warpN = wid >> 2;

    const int z  = blockIdx.z;
    const int z1 = z / Z2, z2 = z - z1 * Z2;
    const int myb = CAUSAL_K ? (int)(gridDim.y - 1 - blockIdx.y) : (int)blockIdx.y;
    const int m0 = myb * BM;
    const int n0 = blockIdx.x * BN;
    if (MASK && n0 > m0) return;
    const bool diag = MASK && (n0 == m0);   // uniform per-CTA

    const __half* Ap = A  + z1 * sA1 + z2 * sA2;
    const __half* Bp = Bm + z1 * sB1 + z2 * sB2;
    float*  Cf = reinterpret_cast<float*>(C)  + z1 * sC1 + z2 * sC2;
    __half* Ch = reinterpret_cast<__half*>(C) + z1 * sC1 + z2 * sC2;
    const float* biasp = BIAS ? (z1 ? bias2 : bias) : nullptr;

    const int Keff = CAUSAL_K ? min(K, m0 + BM) : K;
    const int nk = Keff >> 5;

    const int lr = tid >> 2;
    const int lk = tid & 3;
    const __half* a_g = Ap + (ll)(m0 + lr) * lda + lk * 8;
    const __half* b_g = Bp + (ll)(n0 + lr) * ldb + lk * 8;
    const uint32_t a_off = (uint32_t)(lr * ROWB + lk * 16);
    const uint32_t b_off = a_off;

    #define ISSUE(t)                                                          \
    {                                                                         \
        int k0 = (t) << 5;                                                    \
        uint32_t as = sb + ((t) % 5) * STAGE;                                 \
        uint32_t bs = as + A_TILE;                                            \
        cpasync16(as + a_off, a_g + k0);                                      \
        cpasync16(as + a_off + 64 * ROWB, a_g + k0 + 64 * (ll)lda);           \
        cpasync16(bs + b_off, b_g + k0);                                      \
        if (BN == 128)                                                        \
            cpasync16(bs + b_off + 64 * ROWB, b_g + k0 + 64 * (ll)ldb);       \
    }

    const uint32_t a_lmoff =
        (uint32_t)((warpM * 32 + (lane & 7) + ((lane >> 3) & 1) * 8) * ROWB
                   + ((lane >> 4) & 1) * 16);
    const uint32_t b_lmoff =
        (uint32_t)((warpN * WN + (lane & 7) + ((lane >> 4) & 1) * 8) * ROWB
                   + ((lane >> 3) & 1) * 16);

    float acc[2][NTPW][4];
    #pragma unroll
    for (int i = 0; i < 2; i++)
        #pragma unroll
        for (int j = 0; j < NTPW; j++)
            #pragma unroll
            for (int r = 0; r < 4; r++) acc[i][j][r] = 0.f;

    uint32_t fa[2][2][4];
    uint32_t fb[2][NTPW][2];

    #define LOADF(buf, stg_a, ksv)                                            \
    {                                                                         \
        uint32_t asx = (stg_a);                                               \
        uint32_t bsx = asx + A_TILE;                                          \
        _Pragma("unroll")                                                     \
        for (int mt = 0; mt < 2; mt++)                                        \
            ldsm4(fa[buf][mt], asx + a_lmoff + mt * (16 * ROWB) + (ksv) * 32);\
        _Pragma("unroll")                                                     \
        for (int ng = 0; ng < NGRP; ng++) {                                   \
            uint32_t r4[4];                                                   \
            ldsm4(r4, bsx + b_lmoff + ng * (16 * ROWB) + (ksv) * 32);         \
            fb[buf][2*ng][0] = r4[0]; fb[buf][2*ng][1] = r4[1];               \
            fb[buf][2*ng+1][0] = r4[2]; fb[buf][2*ng+1][1] = r4[3];           \
        }                                                                     \
    }
    #define MMAF(buf)                                                         \
    {                                                                         \
        _Pragma("unroll")                                                     \
        for (int mt = 0; mt < 2; mt++)                                        \
            _Pragma("unroll")                                                 \
            for (int nt = 0; nt < NTPW; nt++)                                 \
                mma_f16(acc[mt][nt], fa[buf][mt], fb[buf][nt]);               \
    }

    ISSUE(0); CP_COMMIT();
    if (1 < nk) { ISSUE(1); } CP_COMMIT();
    if (2 < nk) { ISSUE(2); } CP_COMMIT();

    for (int t = 0; t < nk; t += 2) {
        CP_WAIT1();
        __syncthreads();
        if (t + 3 < nk) { ISSUE(t + 3); }
        CP_COMMIT();
        if (t + 4 < nk) { ISSUE(t + 4); }
        CP_COMMIT();

        uint32_t st0 = sb + ((t)     % 5) * STAGE;
        uint32_t st1 = sb + ((t + 1) % 5) * STAGE;
        LOADF(0, st0, 0);
        LOADF(1, st0, 1);
        MMAF(0);
        LOADF(0, st1, 0);
        MMAF(1);
        LOADF(1, st1, 1);
        MMAF(0);
        MMAF(1);
    }
    #undef ISSUE
    #undef LOADF
    #undef MMAF
    __syncthreads();

    // epilogue
    float*  scr = reinterpret_cast<float*>(dsm);
    __half* stg = reinterpret_cast<__half*>(dsm + 4096);

    #define SC_EPI(DIAG)                                                      \
    {                                                                         \
        _Pragma("unroll")                                                     \
        for (int nt = 0; nt < NTPW; nt++) {                                   \
            int col = n0 + warpN * WN + nt * 8 + (lane & 3) * 2;              \
            float cs0 = 0.f, cs1 = 0.f;                                       \
            _Pragma("unroll")                                                 \
            for (int mt = 0; mt < 2; mt++) {                                  \
                int row0 = m0 + warpM * 32 + mt * 16 + (lane >> 2);           \
                _Pragma("unroll")                                             \
                for (int rr = 0; rr < 2; rr++) {                              \
                    int row = row0 + rr * 8;                                  \
                    float u0 = acc[mt][nt][rr * 2 + 0] * alpha;               \
                    float u1 = acc[mt][nt][rr * 2 + 1] * alpha;               \
                    if (DIAG) {                                               \
                        u0 = (col     > row) ? -60.f : u0;                    \
                        u1 = (col + 1 > row) ? -60.f : u1;                    \
                    }                                                         \
                    __half2 hu = __floats2half2_rn(u0, u1);                   \
                    uint32_t hw;                                              \
                    asm("ex2.approx.f16x2 %0, %1;"                            \
                        : "=r"(hw) : "r"(*reinterpret_cast<uint32_t*>(&hu))); \
                    __half2 hwv = *reinterpret_cast<__half2*>(&hw);           \
                    float2 wf = __half22float2(hwv);                          \
                    cs0 += wf.x; cs1 += wf.y;                                 \
                    *reinterpret_cast<__half2*>(                              \
                        stg + (row - m0) * SROW + (col - n0)) = hwv;          \
                }                                                             \
            }                                                                 \
            _Pragma("unroll")                                                 \
            for (int off = 4; off <= 16; off <<= 1) {                         \
                cs0 += __shfl_xor_sync(0xffffffffu, cs0, off);                \
                cs1 += __shfl_xor_sync(0xffffffffu, cs1, off);                \
            }                                                                 \
            if ((lane >> 2) == 0) {                                           \
                int c = warpN * WN + nt * 8 + lane * 2;                       \
                scr[warpM * BN + c]     = cs0;                                \
                scr[warpM * BN + c + 1] = cs1;                                \
            }                                                                 \
        }                                                                     \
    }

    if (STATS) {
        if (diag) SC_EPI(true) else SC_EPI(false)
        __syncthreads();
        if (tid < BN) {
            float s = scr[tid] + scr[BN + tid] + scr[2 * BN + tid] + scr[3 * BN + tid];
            part[((ll)z * 16 + blockIdx.y) * Tq + n0 + tid] = s;
        }
        const int cr = tid >> 4;
        const int cc = (tid & 15) * 8;
        #pragma unroll
        for (int r = 0; r < 8; r++) {
            int row = cr + r * 16;
            uint4 v = *reinterpret_cast<const uint4*>(stg + row * SROW + cc);
            *reinterpret_cast<uint4*>(Ch + (ll)(m0 + row) * ldc + n0 + cc) = v;
        }
        return;
    }
    #undef SC_EPI

    #pragma unroll
    for (int nt = 0; nt < NTPW; nt++) {
        int col = n0 + warpN * WN + nt * 8 + (lane & 3) * 2;
        float b0 = 0.f, b1 = 0.f;
        if (BIAS) {
            float2 bb = *reinterpret_cast<const float2*>(biasp + col);
            b0 = bb.x; b1 = bb.y;
        }
        #pragma unroll
        for (int mt = 0; mt < 2; mt++) {
            int row0 = m0 + warpM * 32 + mt * 16 + (lane >> 2);
            #pragma unroll
            for (int rr = 0; rr < 2; rr++) {
                int row = row0 + rr * 8;
                float v0 = acc[mt][nt][rr * 2 + 0] * alpha + b0;
                float v1 = acc[mt][nt][rr * 2 + 1] * alpha + b1;
                if (RELU) { v0 = fmaxf(v0, 0.f); v1 = fmaxf(v1, 0.f); }
                if (RES) {
                    float2 rv = *reinterpret_cast<const float2*>(
                        res + (ll)row * ldc + col);
                    v0 += rv.x; v1 += rv.y;
                }
                if (CHALF) {
                    if (CTRANS) {
                        if (VSCALE) {
                            float sc = part[((col >> 6) * Bq + (row >> 11)) * Tq
                                            + (row & 2047)];
                            v0 *= sc; v1 *= sc;
                        }
                        Ch[(ll)col * ldc + row]       = __float2half_rn(v0);
                        Ch[(ll)(col + 1) * ldc + row] = __float2half_rn(v1);
                    } else {
                        *reinterpret_cast<__half2*>(Ch + (ll)row * ldc + col) =
                            __halves2half2(__float2half_rn(v0), __float2half_rn(v1));
                    }
                } else {
                    if (CTRANS) {
                        Cf[(ll)col * ldc + row] = v0;
                        Cf[(ll)(col + 1) * ldc + row] = v1;
                    } else {
                        *reinterpret_cast<float2*>(Cf + (ll)row * ldc + col) =
                            make_float2(v0, v1);
                    }
                }
            }
        }
    }
}

// combine 128-row band partial sums -> 1/sum per column
__global__ __launch_bounds__(256)
void stats_combine_kernel(const float* __restrict__ part,
                          float* __restrict__ stats)
{
    const int z = blockIdx.y;
    const int j = blockIdx.x * 256 + threadIdx.x;
    float s = 0.f;
    for (int p = j >> 7; p < 16; p++)
        s += part[((ll)z * 16 + p) * Tq + j];
    stats[(ll)z * Tq + j] = 1.0f / s;
}

// ---------------------------------------------------------------------------
// Launch sequence
// ---------------------------------------------------------------------------
extern "C" void kernel_launch(void* const* d_in, const int* in_sizes, int n_in,
                              void* d_out, int out_size)
{
    const float* x     = (const float*)d_in[0];
    const float* ln1_w = (const float*)d_in[1];
    const float* Wq    = (const float*)d_in[2];
    const float* bq    = (const float*)d_in[3];
    const float* Wk    = (const float*)d_in[4];
    const float* bk    = (const float*)d_in[5];
    const float* Wv    = (const float*)d_in[6];
    const float* bv    = (const float*)d_in[7];
    const float* Wo    = (const float*)d_in[8];
    const float* bo    = (const float*)d_in[9];
    const float* ln2_w = (const float*)d_in[10];
    const float* W1    = (const float*)d_in[11];
    const float* b1    = (const float*)d_in[12];
    const float* W2    = (const float*)d_in[13];
    const float* b2    = (const float*)d_in[14];
    float* out = (float*)d_out;

    #define GETP(sym, var, ty) void* var##_; cudaGetSymbolAddress(&var##_, sym); \
                               ty* var = (ty*)var##_;
    GETP(g_h, ph, __half)  GETP(g_qk, pqk, __half)  GETP(g_vt, pvt, __half)
    GETP(g_S, pS, __half)
    GETP(g_part, ppart, float)  GETP(g_stats, pstats, float)
    GETP(g_att, patt, __half)  GETP(g_x1, px1, float)  GETP(g_ff, pff, __half)
    GETP(g_wqkt, pwqkt, __half)
    GETP(g_wvt, pwvt, __half)
    GETP(g_wot, pwot, __half)  GETP(g_w1t, pw1t, __half)  GETP(g_w2t, pw2t, __half)
    #undef GETP

    const int SM128 = 5 * (10240 + 10240);   // 102400
    const int SM64  = 5 * (10240 + 5120);    // 76800
    const float AL2E = 0.125f * 1.4426950408889634f;

    auto kQK  = mma_gemm<128,true ,false,false,false,false,false,true ,false,false>;
    auto kV   = mma_gemm<128,true ,false,false,false,false,true ,true ,false,true >;
    auto kSc  = mma_gemm<128,false,false,false,false,true ,false,false,true ,false>;
    auto kAV  = mma_gemm<64 ,false,false,false,true ,false,false,true ,false,false>;
    auto kBR  = mma_gemm<128,true ,false,true ,false,false,false,false,false,false>;
    auto kFF1 = mma_gemm<128,true ,true ,false,false,false,false,true ,false,false>;
    cudaFuncSetAttribute(kQK,  cudaFuncAttributeMaxDynamicSharedMemorySize, SM128);
    cudaFuncSetAttribute(kV,   cudaFuncAttributeMaxDynamicSharedMemorySize, SM128);
    cudaFuncSetAttribute(kSc,  cudaFuncAttributeMaxDynamicSharedMemorySize, SM128);
    cudaFuncSetAttribute(kAV,  cudaFuncAttributeMaxDynamicSharedMemorySize, SM64);
    cudaFuncSetAttribute(kBR,  cudaFuncAttributeMaxDynamicSharedMemorySize, SM128);
    cudaFuncSetAttribute(kFF1, cudaFuncAttributeMaxDynamicSharedMemorySize, SM128);

    // #0 : ALL weight transposes fused
    transpose_all_kernel<<<12288, 256>>>(Wq, Wk, Wv, Wo, W1, W2,
                                         pwqkt, pwvt, pwot, pw1t, pw2t);
    // #1 : LN1
    layernorm_kernel<<<BTq, 256>>>(x, ln1_w, ph);

    // #2 : QK projections (batched z=2)
    {
        dim3 gridQK(Cq / 128, BTq / 128, 2);
        kQK<<<gridQK, 256, SM128>>>(ph, 0, 0, pwqkt, (ll)Cq*Cq, 0, bq, bk, nullptr,
                                    pqk, (ll)BTq*Cq, 0, nullptr,
                                    1, Cq, Cq, Cq, Cq, 1.0f);
    }
    // #3 : scores (diag tiles take compare path via uniform branch)
    {
        dim3 grid(Tq / 128, Tq / 128, Hq * Bq);
        kSc<<<grid, 256, SM128>>>(
            pqk, (ll)HSq, (ll)Tq * Cq,
            pqk + (ll)BTq * Cq, (ll)HSq, (ll)Tq * Cq,
            nullptr, nullptr, nullptr,
            pS, (ll)Bq * Tq * Tq, (ll)Tq * Tq,
            ppart,
            Bq, HSq, Cq, Cq, Tq, AL2E);
    }
    // #4 : combine band sums -> 1/sum
    {
        dim3 g2(Tq / 256, Hq * Bq);
        stats_combine_kernel<<<g2, 256>>>(ppart, pstats);
    }
    // #5 : V projection (writes V^T * 1/sum, fused scaling)
    {
        dim3 gridV(Cq / 128, BTq / 128, 1);
        kV <<<gridV, 256, SM128>>>(ph, 0, 0, pwvt, 0, 0, bv, bv, nullptr,
                                   pvt, 0, 0, pstats,
                                   1, Cq, Cq, Cq, BTq, 1.0f);
    }
    // #6 : att = S @ Vs (plain causal GEMM, heavy tiles first)
    {
        dim3 grid(1, Tq / 128, Hq * Bq);
        kAV<<<grid, 256, SM64>>>(
            pS, (ll)Bq * Tq * Tq, (ll)Tq * Tq,
            pvt, (ll)HSq * BTq, (ll)Tq,
            nullptr, nullptr, nullptr,
            patt, (ll)HSq, (ll)Tq * Cq,
            nullptr,
            Bq, Tq, Tq, BTq, Cq, 1.0f);
    }
    // #7 : x1 = x + att @ Wo + bo (fp32 out)
    {
        dim3 grid(Cq / 128, BTq / 128, 1);
        kBR<<<grid, 256, SM128>>>(patt, 0, 0, pwot, 0, 0, bo, bo, x,
                                  px1, 0, 0, nullptr, 1, Cq, Cq, Cq, Cq, 1.0f);
    }
    // #8 : LN2, #9 : FF1 (half out, BN=128)
    layernorm_kernel<<<BTq, 256>>>(px1, ln2_w, ph);
    {
        dim3 grid(FFq / 128, BTq / 128, 1);
        kFF1<<<grid, 256, SM128>>>(ph, 0, 0, pw1t, 0, 0, b1, b1, nullptr,
                                   pff, 0, 0, nullptr, 1, Cq, Cq, Cq, FFq, 1.0f);
    }
    // #10: out = x1 + ff @ W2 + b2 (fp32 out)
    {
        dim3 grid(Cq / 128, BTq / 128, 1);
        kBR<<<grid, 256, SM128>>>(pff, 0, 0, pw2t, 0, 0, b2, b2, px1,
                                  out, 0, 0, nullptr, 1, FFq, FFq, FFq, Cq, 1.0f);
    }
}